// round 1
// baseline (speedup 1.0000x reference)
#include <cuda_runtime.h>

#define W 960
#define H 512
#define C 16
#define HW (H * W)

__global__ __launch_bounds__(256) void recon_kernel(
    const float* __restrict__ img,   // [C,H,W]
    const float* __restrict__ offx,  // [H,W]
    const float* __restrict__ offy,  // [H,W]
    float* __restrict__ out)         // [C,H,W]
{
    const int w = blockIdx.x * 32 + (threadIdx.x & 31);
    const int h = blockIdx.y * 8 + (threadIdx.x >> 5);
    if (w >= W || h >= H) return;

    // --- per-neighbor bilinear params (fully unrolled -> registers) ---
    int   base[9];
    float w00[9], w10[9], w01[9], w11[9];

    const float fw = (float)w;
    const float fh = (float)h;

#pragma unroll
    for (int di = 0; di < 3; di++) {
        int hh = h + di - 1;
        hh = (hh < 0) ? -hh : ((hh >= H) ? (2 * H - 2 - hh) : hh);
#pragma unroll
        for (int dj = 0; dj < 3; dj++) {
            int ww = w + dj - 1;
            ww = (ww < 0) ? -ww : ((ww >= W) ? (2 * W - 2 - ww) : ww);
            const int oidx = hh * W + ww;
            const float sx = __ldg(offx + oidx);
            const float sy = __ldg(offy + oidx);

            // replicate reference arithmetic exactly
            float cx = fminf(fmaxf(fw - sx, 0.0f), (float)(W - 1));
            float cy = fminf(fmaxf(fh - sy, 0.0f), (float)(H - 1));
            float gx = (cx - (float)(W / 2)) / (float)(W / 2);
            float gy = (cy - (float)(H / 2)) / (float)(H / 2);
            float ix = (gx + 1.0f) * 0.5f * (float)(W - 1);
            float iy = (gy + 1.0f) * 0.5f * (float)(H - 1);

            float x0f = floorf(ix);
            float y0f = floorf(iy);
            float wx1 = ix - x0f;
            float wy1 = iy - y0f;
            float wx0 = 1.0f - wx1;
            float wy0 = 1.0f - wy1;

            const int n = di * 3 + dj;
            base[n] = (int)y0f * W + (int)x0f;
            w00[n] = wx0 * wy0;
            w10[n] = wx1 * wy0;
            w01[n] = wx0 * wy1;
            w11[n] = wx1 * wy1;
        }
    }

    const int pix = h * W + w;
    const float inv9 = 1.0f / 9.0f;

    // --- channel loop: 9 bilinear taps each, unroll 2 for MLP ---
#pragma unroll 2
    for (int c = 0; c < C; c++) {
        const float* __restrict__ p = img + c * HW;
        float acc = 0.0f;
#pragma unroll
        for (int n = 0; n < 9; n++) {
            const int b = base[n];
            const float v00 = __ldg(p + b);
            const float v10 = __ldg(p + b + 1);
            const float v01 = __ldg(p + b + W);
            const float v11 = __ldg(p + b + W + 1);
            acc += v00 * w00[n] + v10 * w10[n] + v01 * w01[n] + v11 * w11[n];
        }
        out[c * HW + pix] = acc * inv9;
    }
}

extern "C" void kernel_launch(void* const* d_in, const int* in_sizes, int n_in,
                              void* d_out, int out_size)
{
    const float* img  = (const float*)d_in[0];  // right_input [1,16,512,960]
    const float* offx = (const float*)d_in[1];  // offset_x    [1,1,512,960]
    const float* offy = (const float*)d_in[2];  // offset_y    [1,1,512,960]
    float* out = (float*)d_out;                 // [1,16,512,960]

    dim3 block(256);
    dim3 grid(W / 32, H / 8);  // 960/32=30, 512/8=64
    recon_kernel<<<grid, block>>>(img, offx, offy, out);
}